// round 4
// baseline (speedup 1.0000x reference)
#include <cuda_runtime.h>
#include <cstdint>
#include <cstddef>

// ---------------- problem constants ----------------
#define B_WIN   4096
#define N_TOK   49
#define C_DIM   128
#define NH      4
#define HD      32
#define NWIN    64
#define SCALE   0.17677669529663687f

// ---------------- persistent device scratch ----------------
__device__ __align__(16) uint32_t g_w1[128 * 384];           // qkv_w, tf32
__device__ __align__(16) uint32_t g_w2[128 * 128];           // proj_w, tf32
__device__ __align__(16) float    g_bm[NWIN * N_TOK * N_TOK]; // bias[rel]+mask

// ---------------- helpers ----------------
__device__ __forceinline__ uint32_t f2tf32(float f) {
    uint32_t r;
    asm("cvt.rna.tf32.f32 %0, %1;" : "=r"(r) : "f"(f));
    return r;
}
__device__ __forceinline__ void mma_tf32(float c[4], const uint32_t a[4], const uint32_t b[2]) {
    asm volatile(
        "mma.sync.aligned.m16n8k8.row.col.f32.tf32.tf32.f32 "
        "{%0,%1,%2,%3}, {%4,%5,%6,%7}, {%8,%9}, {%0,%1,%2,%3};"
        : "+f"(c[0]), "+f"(c[1]), "+f"(c[2]), "+f"(c[3])
        : "r"(a[0]), "r"(a[1]), "r"(a[2]), "r"(a[3]), "r"(b[0]), "r"(b[1]));
}
__device__ __forceinline__ void cp_async16(uint32_t smem_dst, const void* gsrc) {
    asm volatile("cp.async.ca.shared.global [%0], [%1], 16;\n" :: "r"(smem_dst), "l"(gsrc));
}
__device__ __forceinline__ void cp_commit() { asm volatile("cp.async.commit_group;\n"); }
template <int N>
__device__ __forceinline__ void cp_wait() { asm volatile("cp.async.wait_group %0;\n" :: "n"(N)); }

// ---------------- prep: convert weights to tf32, build bias+mask table ----------------
__global__ void prep_kernel(const float* __restrict__ mask,
                            const float* __restrict__ bias_table,
                            const int*   __restrict__ rel_index,
                            const float* __restrict__ qkv_w,
                            const float* __restrict__ proj_w)
{
    int idx = blockIdx.x * 256 + threadIdx.x;
    const int n1 = 128 * 384, n2 = 128 * 128, n3 = NWIN * N_TOK * N_TOK;
    if (idx < n1) {
        g_w1[idx] = f2tf32(qkv_w[idx]);
    } else if (idx < n1 + n2) {
        g_w2[idx - n1] = f2tf32(proj_w[idx - n1]);
    } else if (idx < n1 + n2 + n3) {
        int t = idx - n1 - n2;
        g_bm[t] = mask[t] + bias_table[rel_index[t % (N_TOK * N_TOK)]];
    }
}

// ---------------- smem layout (uint32 words) ----------------
// P1: As/Os [64][132]                 ->  8448 words
// Qs [64][132], Ks [64][132]          -> 16896 words
// Vs [64][136]                        ->  8704 words
// P2: max(Bs 2*16*392, S 4*64*60, Ws 2*32*136) -> 15360 words
#define OFF_P1  0
#define OFF_QS  8448
#define OFF_KS  16896
#define OFF_VS  25344
#define OFF_P2  34048
#define SMEM_WORDS 49408   // 197632 bytes

__global__ __launch_bounds__(256, 1)
void fused_kernel(const float* __restrict__ x,
                  const float* __restrict__ qkv_b,
                  const float* __restrict__ proj_b,
                  float* __restrict__ out)
{
    extern __shared__ uint32_t sm[];
    uint32_t* As = sm + OFF_P1;   // [64][132] tf32 of x (padded)
    uint32_t* Qs = sm + OFF_QS;   // [64][132]
    uint32_t* Ks = sm + OFF_KS;   // [64][132]
    uint32_t* Vs = sm + OFF_VS;   // [64][136]
    uint32_t* P2 = sm + OFF_P2;   // Bs / S / Ws

    const int w    = blockIdx.x;
    const int tid  = threadIdx.x;
    const int lane = tid & 31;
    const int warp = tid >> 5;

    // ============ phase 1: qkv = x @ qkv_w + qkv_b (tf32 MMA) ============
    // B staging: half-chunks of K=16 rows of g_w1, double-buffered in P2.
    auto stage_w1 = [&](int buf, int k0) {
        const int row = tid >> 4;          // 16 rows, 16 thr/row
        const int ts  = tid & 15;
        #pragma unroll
        for (int p = 0; p < 6; p++) {
            int seg = ts + p * 16;         // 96 segs of 16B per row
            uint32_t dst = (uint32_t)__cvta_generic_to_shared(
                &P2[buf * 16 * 392 + row * 392 + seg * 4]);
            cp_async16(dst, &g_w1[(k0 + row) * 384 + seg * 4]);
        }
        cp_commit();
    };

    stage_w1(0, 0);

    // load x tile -> As (tf32), zero-pad rows 49..63
    const float* xb = x + (size_t)w * N_TOK * 128;
    for (int t = tid; t < 64 * 32; t += 256) {
        int r = t >> 5, c4 = (t & 31) * 4;
        uint4 u;
        if (r < N_TOK) {
            float4 v = *(const float4*)&xb[r * 128 + c4];
            u.x = f2tf32(v.x); u.y = f2tf32(v.y); u.z = f2tf32(v.z); u.w = f2tf32(v.w);
        } else {
            u.x = u.y = u.z = u.w = 0u;
        }
        *(uint4*)&As[r * 132 + c4] = u;
    }

    {
        const int wm = warp >> 2;      // 0..1  (32 M-rows each)
        const int wn = warp & 3;       // 0..3  (96 N-cols each)
        float acc[2][12][4];
        #pragma unroll
        for (int a = 0; a < 2; a++)
            #pragma unroll
            for (int b = 0; b < 12; b++)
                #pragma unroll
                for (int r = 0; r < 4; r++) acc[a][b][r] = 0.f;

        #pragma unroll
        for (int hc = 0; hc < 8; hc++) {
            if (hc < 7) stage_w1((hc + 1) & 1, (hc + 1) * 16);
            if (hc < 7) cp_wait<1>(); else cp_wait<0>();
            __syncthreads();
            const uint32_t* bs = &P2[(hc & 1) * 16 * 392];

            #pragma unroll
            for (int kk = 0; kk < 2; kk++) {
                const int kg = hc * 16 + kk * 8;       // global k
                uint32_t af[2][4];
                #pragma unroll
                for (int mt = 0; mt < 2; mt++) {
                    int row = wm * 32 + mt * 16 + (lane >> 2);
                    int col = kg + (lane & 3);
                    af[mt][0] = As[row * 132 + col];
                    af[mt][1] = As[(row + 8) * 132 + col];
                    af[mt][2] = As[row * 132 + col + 4];
                    af[mt][3] = As[(row + 8) * 132 + col + 4];
                }
                #pragma unroll
                for (int nt = 0; nt < 12; nt++) {
                    int col = wn * 96 + nt * 8 + (lane >> 2);
                    int row = kk * 8 + (lane & 3);
                    uint32_t bf[2] = { bs[row * 392 + col], bs[(row + 4) * 392 + col] };
                    mma_tf32(acc[0][nt], af[0], bf);
                    mma_tf32(acc[1][nt], af[1], bf);
                }
            }
            __syncthreads();
        }

        // epilogue: +bias, scale q, scatter to Qs/Ks/Vs as tf32
        #pragma unroll
        for (int mt = 0; mt < 2; mt++) {
            #pragma unroll
            for (int nt = 0; nt < 12; nt++) {
                int nb = wn * 96 + nt * 8 + (lane & 3) * 2;
                #pragma unroll
                for (int half = 0; half < 2; half++) {
                    int m = wm * 32 + mt * 16 + (lane >> 2) + half * 8;
                    #pragma unroll
                    for (int e = 0; e < 2; e++) {
                        int n = nb + e;
                        float v = acc[mt][nt][half * 2 + e] + __ldg(&qkv_b[n]);
                        if (n < 128)      Qs[m * 132 + n]        = f2tf32(v * SCALE);
                        else if (n < 256) Ks[m * 132 + (n - 128)] = f2tf32(v);
                        else              Vs[m * 136 + (n - 256)] = f2tf32(v);
                    }
                }
            }
        }
    }
    __syncthreads();

    // ============ phase 2: attention (2 warps per head) ============
    const int h  = warp >> 1;          // head
    const int mh = warp & 1;           // m-half (rows mh*32 .. +31)
    uint32_t* S  = P2 + h * 64 * 60;   // [64][60] per head
    const float* bm = g_bm + (size_t)(w & (NWIN - 1)) * N_TOK * N_TOK;

    {   // scores: S = q k^T + bm  (pad cols/rows -> -1e30)
        uint32_t af[2][4][4];
        #pragma unroll
        for (int mt = 0; mt < 2; mt++)
            #pragma unroll
            for (int ks = 0; ks < 4; ks++) {
                int row = mh * 32 + mt * 16 + (lane >> 2);
                int col = h * HD + ks * 8 + (lane & 3);
                af[mt][ks][0] = Qs[row * 132 + col];
                af[mt][ks][1] = Qs[(row + 8) * 132 + col];
                af[mt][ks][2] = Qs[row * 132 + col + 4];
                af[mt][ks][3] = Qs[(row + 8) * 132 + col + 4];
            }
        #pragma unroll
        for (int nt = 0; nt < 7; nt++) {
            float c[2][4];
            #pragma unroll
            for (int mt = 0; mt < 2; mt++)
                #pragma unroll
                for (int r = 0; r < 4; r++) c[mt][r] = 0.f;
            #pragma unroll
            for (int ks = 0; ks < 4; ks++) {
                int nc = nt * 8 + (lane >> 2);
                int kr = h * HD + ks * 8 + (lane & 3);
                uint32_t bf[2] = { Ks[nc * 132 + kr], Ks[nc * 132 + kr + 4] };
                mma_tf32(c[0], af[0][ks], bf);
                mma_tf32(c[1], af[1][ks], bf);
            }
            #pragma unroll
            for (int mt = 0; mt < 2; mt++)
                #pragma unroll
                for (int half = 0; half < 2; half++) {
                    int i = mh * 32 + mt * 16 + (lane >> 2) + half * 8;
                    int j = nt * 8 + 2 * (lane & 3);
                    float v0 = c[mt][half * 2], v1 = c[mt][half * 2 + 1];
                    float o0 = (i < N_TOK && j     < N_TOK) ? v0 + bm[i * N_TOK + j]     : -1e30f;
                    float o1 = (i < N_TOK && j + 1 < N_TOK) ? v1 + bm[i * N_TOK + j + 1] : -1e30f;
                    S[i * 60 + j]     = __float_as_uint(o0);
                    S[i * 60 + j + 1] = __float_as_uint(o1);
                }
        }
    }
    __syncthreads();

    // softmax (warp per row, all heads x rows), write back tf32 bits (P)
    for (int hh = 0; hh < NH; hh++) {
        uint32_t* Sh = P2 + hh * 64 * 60;
        for (int i = warp; i < N_TOK; i += 8) {
            float v1 = __uint_as_float(Sh[i * 60 + lane]);
            float v2 = (lane < 24) ? __uint_as_float(Sh[i * 60 + 32 + lane]) : -1e30f;
            float mx = fmaxf(v1, v2);
            #pragma unroll
            for (int o = 16; o > 0; o >>= 1) mx = fmaxf(mx, __shfl_xor_sync(0xffffffffu, mx, o));
            float e1 = __expf(v1 - mx);
            float e2 = (lane < 24) ? __expf(v2 - mx) : 0.f;
            float s = e1 + e2;
            #pragma unroll
            for (int o = 16; o > 0; o >>= 1) s += __shfl_xor_sync(0xffffffffu, s, o);
            float inv = 1.f / s;
            Sh[i * 60 + lane] = f2tf32(e1 * inv);
            if (lane < 24) Sh[i * 60 + 32 + lane] = f2tf32(e2 * inv);
        }
    }
    __syncthreads();

    // O = P @ V -> Os (tf32), Os lives where As was
    uint32_t* Os = As;
    #pragma unroll
    for (int mt = 0; mt < 2; mt++) {
        uint32_t af[7][4];
        #pragma unroll
        for (int ks = 0; ks < 7; ks++) {
            int row = mh * 32 + mt * 16 + (lane >> 2);
            int col = ks * 8 + (lane & 3);
            af[ks][0] = S[row * 60 + col];
            af[ks][1] = S[(row + 8) * 60 + col];
            af[ks][2] = S[row * 60 + col + 4];
            af[ks][3] = S[(row + 8) * 60 + col + 4];
        }
        #pragma unroll
        for (int nt = 0; nt < 4; nt++) {
            float c[4] = {0.f, 0.f, 0.f, 0.f};
            #pragma unroll
            for (int ks = 0; ks < 7; ks++) {
                int kr = ks * 8 + (lane & 3);
                int nc = nt * 8 + (lane >> 2);
                uint32_t bf[2] = { Vs[kr * 136 + h * HD + nc], Vs[(kr + 4) * 136 + h * HD + nc] };
                mma_tf32(c, af[ks], bf);
            }
            int row = mh * 32 + mt * 16 + (lane >> 2);
            int d   = h * HD + nt * 8 + 2 * (lane & 3);
            Os[row * 132 + d]           = f2tf32(c[0]);
            Os[row * 132 + d + 1]       = f2tf32(c[1]);
            Os[(row + 8) * 132 + d]     = f2tf32(c[2]);
            Os[(row + 8) * 132 + d + 1] = f2tf32(c[3]);
        }
    }
    __syncthreads();   // Os complete; S dead -> P2 reusable for Ws

    // ============ phase 3: out = O @ proj_w + proj_b ============
    auto stage_w2 = [&](int buf, int k0) {
        const int row = tid >> 3;          // 32 rows, 8 thr/row
        const int ts  = tid & 7;
        #pragma unroll
        for (int p = 0; p < 4; p++) {
            int seg = ts + p * 8;          // 32 segs of 16B per row
            uint32_t dst = (uint32_t)__cvta_generic_to_shared(
                &P2[buf * 32 * 136 + row * 136 + seg * 4]);
            cp_async16(dst, &g_w2[(k0 + row) * 128 + seg * 4]);
        }
        cp_commit();
    };

    {
        const int wm = warp >> 2;   // 0..1
        const int wn = warp & 3;    // 0..3 (32 cols each)
        float acc[2][4][4];
        #pragma unroll
        for (int a = 0; a < 2; a++)
            #pragma unroll
            for (int b = 0; b < 4; b++)
                #pragma unroll
                for (int r = 0; r < 4; r++) acc[a][b][r] = 0.f;

        stage_w2(0, 0);
        #pragma unroll
        for (int ch = 0; ch < 4; ch++) {
            if (ch < 3) stage_w2((ch + 1) & 1, (ch + 1) * 32);
            if (ch < 3) cp_wait<1>(); else cp_wait<0>();
            __syncthreads();
            const uint32_t* ws = &P2[(ch & 1) * 32 * 136];
            #pragma unroll
            for (int kk = 0; kk < 4; kk++) {
                const int kg = ch * 32 + kk * 8;
                uint32_t af[2][4];
                #pragma unroll
                for (int mt = 0; mt < 2; mt++) {
                    int row = wm * 32 + mt * 16 + (lane >> 2);
                    int col = kg + (lane & 3);
                    af[mt][0] = Os[row * 132 + col];
                    af[mt][1] = Os[(row + 8) * 132 + col];
                    af[mt][2] = Os[row * 132 + col + 4];
                    af[mt][3] = Os[(row + 8) * 132 + col + 4];
                }
                #pragma unroll
                for (int nt = 0; nt < 4; nt++) {
                    int col = wn * 32 + nt * 8 + (lane >> 2);
                    int row = kk * 8 + (lane & 3);
                    uint32_t bf[2] = { ws[row * 136 + col], ws[(row + 4) * 136 + col] };
                    mma_tf32(acc[0][nt], af[0], bf);
                    mma_tf32(acc[1][nt], af[1], bf);
                }
            }
            __syncthreads();
        }

        float* ob = out + (size_t)w * N_TOK * C_DIM;
        #pragma unroll
        for (int mt = 0; mt < 2; mt++) {
            #pragma unroll
            for (int nt = 0; nt < 4; nt++) {
                int n = wn * 32 + nt * 8 + (lane & 3) * 2;
                float b0 = __ldg(&proj_b[n]), b1 = __ldg(&proj_b[n + 1]);
                int m = wm * 32 + mt * 16 + (lane >> 2);
                if (m < N_TOK)
                    *(float2*)&ob[m * C_DIM + n] =
                        make_float2(acc[mt][nt][0] + b0, acc[mt][nt][1] + b1);
                if (m + 8 < N_TOK)
                    *(float2*)&ob[(m + 8) * C_DIM + n] =
                        make_float2(acc[mt][nt][2] + b0, acc[mt][nt][3] + b1);
            }
        }
    }
}

// ---------------- launch ----------------
extern "C" void kernel_launch(void* const* d_in, const int* in_sizes, int n_in,
                              void* d_out, int out_size)
{
    const float* x          = (const float*)d_in[0];
    const float* mask       = (const float*)d_in[1];
    const float* qkv_w      = (const float*)d_in[2];
    const float* qkv_b      = (const float*)d_in[3];
    const float* proj_w     = (const float*)d_in[4];
    const float* proj_b     = (const float*)d_in[5];
    const float* bias_table = (const float*)d_in[6];
    const int*   rel_index  = (const int*)d_in[7];
    float*       out        = (float*)d_out;

    static bool attr_set = false;
    if (!attr_set) {
        cudaFuncSetAttribute(fused_kernel,
                             cudaFuncAttributeMaxDynamicSharedMemorySize,
                             SMEM_WORDS * 4);
        attr_set = true;
    }

    const int prep_total = 128 * 384 + 128 * 128 + NWIN * N_TOK * N_TOK;
    prep_kernel<<<(prep_total + 255) / 256, 256>>>(mask, bias_table, rel_index, qkv_w, proj_w);

    fused_kernel<<<B_WIN, 256, SMEM_WORDS * 4>>>(x, qkv_b, proj_b, out);
}

// round 5
// speedup vs baseline: 1.6255x; 1.6255x over previous
#include <cuda_runtime.h>
#include <cstdint>
#include <cstddef>

// ---------------- problem constants ----------------
#define B_WIN   4096
#define N_TOK   49
#define C_DIM   128
#define NH      4
#define HD      32
#define NWIN    64
#define M_ROWS  (B_WIN * N_TOK)        // 200704
#define SCALE   0.17677669529663687f   // 32^-0.5

// ---------------- scratch (no cudaMalloc allowed) ----------------
__device__ __align__(16) float g_qkv[(size_t)M_ROWS * 384];  // tf32 BITS, q pre-scaled
__device__ __align__(16) float g_att[(size_t)M_ROWS * 128];  // fp32
__device__ __align__(16) float g_bm[NWIN * N_TOK * N_TOK];   // bias[rel] + mask

// ---------------- helpers ----------------
__device__ __forceinline__ uint32_t f2tf32(float f) {
    uint32_t r;
    asm("cvt.rna.tf32.f32 %0, %1;" : "=r"(r) : "f"(f));
    return r;
}
__device__ __forceinline__ void mma_tf32(float c[4], const uint32_t a[4], const uint32_t b[2]) {
    asm volatile(
        "mma.sync.aligned.m16n8k8.row.col.f32.tf32.tf32.f32 "
        "{%0,%1,%2,%3}, {%4,%5,%6,%7}, {%8,%9}, {%0,%1,%2,%3};"
        : "+f"(c[0]), "+f"(c[1]), "+f"(c[2]), "+f"(c[3])
        : "r"(a[0]), "r"(a[1]), "r"(a[2]), "r"(a[3]), "r"(b[0]), "r"(b[1]));
}
__device__ __forceinline__ void cp_async16(uint32_t smem_dst, const void* gsrc) {
    asm volatile("cp.async.ca.shared.global [%0], [%1], 16;\n" :: "r"(smem_dst), "l"(gsrc));
}
__device__ __forceinline__ void cp_commit() { asm volatile("cp.async.commit_group;\n"); }
template <int N>
__device__ __forceinline__ void cp_wait() { asm volatile("cp.async.wait_group %0;\n" :: "n"(N)); }

// ---------------- pre-kernel: g_bm = bias_table[rel_index] + mask ----------------
__global__ void bm_kernel(const float* __restrict__ mask,
                          const float* __restrict__ bias_table,
                          const int*   __restrict__ rel_index)
{
    int idx = blockIdx.x * 256 + threadIdx.x;
    if (idx >= NWIN * N_TOK * N_TOK) return;
    int r = idx % (N_TOK * N_TOK);
    g_bm[idx] = mask[idx] + bias_table[rel_index[r]];
}

// ---------------- tf32 GEMM, cp.async double-buffered --------------------------------
// out[M,NCOLS] = A[M,128] @ W[128,NCOLS] + bias. Tile 128x128, K chunks of 32.
// QKV_OUT: store tf32 bits, q (n<128) pre-scaled by SCALE.
#define AS_STRIDE 36
#define BS_STRIDE 136
#define AS_WORDS (128 * AS_STRIDE)
#define BS_WORDS (32 * BS_STRIDE)

template <int NCOLS, bool QKV_OUT>
__global__ __launch_bounds__(256, 2)
void gemm_tc_kernel(const float* __restrict__ A,
                    const float* __restrict__ W,
                    const float* __restrict__ bias,
                    float* __restrict__ out)
{
    extern __shared__ float smem[];
    float* As = smem;                 // [2][AS_WORDS]
    float* Bs = smem + 2 * AS_WORDS;  // [2][BS_WORDS]

    const int tid  = threadIdx.x;
    const int lane = tid & 31;
    const int warp = tid >> 5;
    const int wm   = warp >> 2;
    const int wn   = warp & 3;
    const int m0   = blockIdx.x * 128;
    const int n0   = blockIdx.y * 128;

    float acc[4][4][4];
    #pragma unroll
    for (int i = 0; i < 4; i++)
        #pragma unroll
        for (int j = 0; j < 4; j++)
            #pragma unroll
            for (int r = 0; r < 4; r++) acc[i][j][r] = 0.f;

    auto stage_load = [&](int st, int k0) {
        #pragma unroll
        for (int p = 0; p < 4; p++) {
            int idx = tid + p * 256;
            int row = idx >> 3, seg = idx & 7;
            uint32_t dst = (uint32_t)__cvta_generic_to_shared(
                &As[st * AS_WORDS + row * AS_STRIDE + seg * 4]);
            cp_async16(dst, &A[(size_t)(m0 + row) * 128 + k0 + seg * 4]);
        }
        #pragma unroll
        for (int p = 0; p < 4; p++) {
            int idx = tid + p * 256;
            int row = idx >> 5, seg = idx & 31;
            uint32_t dst = (uint32_t)__cvta_generic_to_shared(
                &Bs[st * BS_WORDS + row * BS_STRIDE + seg * 4]);
            cp_async16(dst, &W[(size_t)(k0 + row) * NCOLS + n0 + seg * 4]);
        }
        cp_commit();
    };

    stage_load(0, 0);

    #pragma unroll
    for (int ch = 0; ch < 4; ch++) {
        if (ch < 3) stage_load((ch + 1) & 1, (ch + 1) * 32);
        if (ch < 3) cp_wait<1>(); else cp_wait<0>();
        __syncthreads();

        const float* as = &As[(ch & 1) * AS_WORDS];
        const float* bs = &Bs[(ch & 1) * BS_WORDS];

        #pragma unroll
        for (int kk = 0; kk < 4; kk++) {
            const int k = kk * 8;
            uint32_t af[4][4];
            #pragma unroll
            for (int mt = 0; mt < 4; mt++) {
                int row = wm * 64 + mt * 16 + (lane >> 2);
                int col = k + (lane & 3);
                af[mt][0] = f2tf32(as[row * AS_STRIDE + col]);
                af[mt][1] = f2tf32(as[(row + 8) * AS_STRIDE + col]);
                af[mt][2] = f2tf32(as[row * AS_STRIDE + col + 4]);
                af[mt][3] = f2tf32(as[(row + 8) * AS_STRIDE + col + 4]);
            }
            uint32_t bf[4][2];
            #pragma unroll
            for (int nt = 0; nt < 4; nt++) {
                int col = wn * 32 + nt * 8 + (lane >> 2);
                int row = k + (lane & 3);
                bf[nt][0] = f2tf32(bs[row * BS_STRIDE + col]);
                bf[nt][1] = f2tf32(bs[(row + 4) * BS_STRIDE + col]);
            }
            #pragma unroll
            for (int mt = 0; mt < 4; mt++)
                #pragma unroll
                for (int nt = 0; nt < 4; nt++)
                    mma_tf32(acc[mt][nt], af[mt], bf[nt]);
        }
        __syncthreads();
    }

    #pragma unroll
    for (int mt = 0; mt < 4; mt++) {
        #pragma unroll
        for (int nt = 0; nt < 4; nt++) {
            int m = m0 + wm * 64 + mt * 16 + (lane >> 2);
            int n = n0 + wn * 32 + nt * 8 + (lane & 3) * 2;
            float b0 = bias[n], b1 = bias[n + 1];
            float v00 = acc[mt][nt][0] + b0, v01 = acc[mt][nt][1] + b1;
            float v10 = acc[mt][nt][2] + b0, v11 = acc[mt][nt][3] + b1;
            if (QKV_OUT) {
                // q columns (n < 128) pre-scaled; store tf32 bits
                float s0 = (n     < 128) ? SCALE : 1.f;
                float s1 = (n + 1 < 128) ? SCALE : 1.f;
                *(float2*)&out[(size_t)m * NCOLS + n] = make_float2(
                    __uint_as_float(f2tf32(v00 * s0)), __uint_as_float(f2tf32(v01 * s1)));
                *(float2*)&out[(size_t)(m + 8) * NCOLS + n] = make_float2(
                    __uint_as_float(f2tf32(v10 * s0)), __uint_as_float(f2tf32(v11 * s1)));
            } else {
                *(float2*)&out[(size_t)m * NCOLS + n] = make_float2(v00, v01);
                *(float2*)&out[(size_t)(m + 8) * NCOLS + n] = make_float2(v10, v11);
            }
        }
    }
}

// ---------------- tensor-core window attention, single-barrier ----------------------
// One block per (window, head). 4 warps; warp owns 16 m-rows through ALL phases.
#define QS 36
#define VS 40
#define SS 60

__global__ __launch_bounds__(128)
void attn_tc_kernel()
{
    const int w = blockIdx.x;
    const int h = blockIdx.y;

    __shared__ __align__(16) uint32_t Qs[64 * QS];
    __shared__ __align__(16) uint32_t Ks[64 * QS];
    __shared__ __align__(16) uint32_t Vs[64 * VS];
    __shared__ __align__(16) uint32_t S [64 * SS];

    const int tid  = threadIdx.x;
    const int lane = tid & 31;
    const int warp = tid >> 5;

    // ---- async-stage q/k/v (already tf32 bits, q pre-scaled) ----
    const float* bq = g_qkv + (size_t)w * N_TOK * 384 + h * HD;
    for (int t = tid; t < N_TOK * 8 * 3; t += 128) {
        int tt = t / (N_TOK * 8);
        int rem = t - tt * (N_TOK * 8);
        int n = rem >> 3, seg = rem & 7;
        const float* src = bq + n * 384 + tt * 128 + seg * 4;
        uint32_t dst;
        if (tt == 0)      dst = (uint32_t)__cvta_generic_to_shared(&Qs[n * QS + seg * 4]);
        else if (tt == 1) dst = (uint32_t)__cvta_generic_to_shared(&Ks[n * QS + seg * 4]);
        else              dst = (uint32_t)__cvta_generic_to_shared(&Vs[n * VS + seg * 4]);
        cp_async16(dst, src);
    }
    cp_commit();
    // zero pad rows 49..63 (V pad must be zero to avoid 0*garbage=NaN in PV)
    for (int t = tid; t < 15 * HD; t += 128) {
        int n = N_TOK + (t >> 5), d = t & 31;
        Qs[n * QS + d] = 0u;
        Ks[n * QS + d] = 0u;
        Vs[n * VS + d] = 0u;
    }
    cp_wait<0>();
    __syncthreads();   // the ONLY block barrier

    // ---- scores for this warp's 16 rows: S = q k^T + bm ----
    const float* bm = g_bm + (size_t)(w & (NWIN - 1)) * N_TOK * N_TOK;
    const int rA = warp * 16 + (lane >> 2);
    {
        uint32_t af[4][4];
        #pragma unroll
        for (int ks = 0; ks < 4; ks++) {
            int col = ks * 8 + (lane & 3);
            af[ks][0] = Qs[rA * QS + col];
            af[ks][1] = Qs[(rA + 8) * QS + col];
            af[ks][2] = Qs[rA * QS + col + 4];
            af[ks][3] = Qs[(rA + 8) * QS + col + 4];
        }
        #pragma unroll
        for (int nt = 0; nt < 7; nt++) {
            float c[4] = {0.f, 0.f, 0.f, 0.f};
            #pragma unroll
            for (int ks = 0; ks < 4; ks++) {
                int nc = nt * 8 + (lane >> 2);
                int kr = ks * 8 + (lane & 3);
                uint32_t bf[2] = { Ks[nc * QS + kr], Ks[nc * QS + kr + 4] };
                mma_tf32(c, af[ks], bf);
            }
            const int j = nt * 8 + 2 * (lane & 3);
            #pragma unroll
            for (int half = 0; half < 2; half++) {
                int ii = rA + half * 8;
                float o0, o1;
                if (ii < N_TOK) {
                    o0 = (j     < N_TOK) ? c[half * 2]     + __ldg(&bm[ii * N_TOK + j])     : -1e30f;
                    o1 = (j + 1 < N_TOK) ? c[half * 2 + 1] + __ldg(&bm[ii * N_TOK + j + 1]) : -1e30f;
                } else { o0 = 0.f; o1 = 0.f; }
                S[ii * SS + j]     = __float_as_uint(o0);
                S[ii * SS + j + 1] = __float_as_uint(o1);
            }
        }
    }
    __syncwarp();

    // ---- softmax on this warp's own rows, writeback tf32 bits (P) ----
    {
        const int rend = min(warp * 16 + 16, N_TOK);
        for (int i = warp * 16; i < rend; i++) {
            float v1 = __uint_as_float(S[i * SS + lane]);
            float v2 = (lane < 24) ? __uint_as_float(S[i * SS + 32 + lane]) : -1e30f;
            float mx = fmaxf(v1, v2);
            #pragma unroll
            for (int o = 16; o > 0; o >>= 1) mx = fmaxf(mx, __shfl_xor_sync(0xffffffffu, mx, o));
            float e1 = __expf(v1 - mx);
            float e2 = (lane < 24) ? __expf(v2 - mx) : 0.f;
            float s = e1 + e2;
            #pragma unroll
            for (int o = 16; o > 0; o >>= 1) s += __shfl_xor_sync(0xffffffffu, s, o);
            float inv = 1.f / s;
            S[i * SS + lane] = f2tf32(e1 * inv);
            if (lane < 24) S[i * SS + 32 + lane] = f2tf32(e2 * inv);
        }
    }
    __syncwarp();

    // ---- O = P @ V for this warp's rows ----
    {
        uint32_t pf[7][4];
        #pragma unroll
        for (int ks = 0; ks < 7; ks++) {
            int col = ks * 8 + (lane & 3);
            pf[ks][0] = S[rA * SS + col];
            pf[ks][1] = S[(rA + 8) * SS + col];
            pf[ks][2] = S[rA * SS + col + 4];
            pf[ks][3] = S[(rA + 8) * SS + col + 4];
        }
        float* outb = g_att + (size_t)w * N_TOK * C_DIM + h * HD;
        #pragma unroll
        for (int nt = 0; nt < 4; nt++) {
            float c[4] = {0.f, 0.f, 0.f, 0.f};
            #pragma unroll
            for (int ks = 0; ks < 7; ks++) {
                int kr = ks * 8 + (lane & 3);
                int nc = nt * 8 + (lane >> 2);
                uint32_t bf[2] = { Vs[kr * VS + nc], Vs[(kr + 4) * VS + nc] };
                mma_tf32(c, pf[ks], bf);
            }
            const int d = nt * 8 + 2 * (lane & 3);
            if (rA < N_TOK)
                *(float2*)&outb[rA * C_DIM + d] = make_float2(c[0], c[1]);
            if (rA + 8 < N_TOK)
                *(float2*)&outb[(rA + 8) * C_DIM + d] = make_float2(c[2], c[3]);
        }
    }
}

// ---------------- launch ----------------
extern "C" void kernel_launch(void* const* d_in, const int* in_sizes, int n_in,
                              void* d_out, int out_size)
{
    const float* x          = (const float*)d_in[0];
    const float* mask       = (const float*)d_in[1];
    const float* qkv_w      = (const float*)d_in[2];
    const float* qkv_b      = (const float*)d_in[3];
    const float* proj_w     = (const float*)d_in[4];
    const float* proj_b     = (const float*)d_in[5];
    const float* bias_table = (const float*)d_in[6];
    const int*   rel_index  = (const int*)d_in[7];
    float*       out        = (float*)d_out;

    void* qkv_ptr = nullptr;
    void* att_ptr = nullptr;
    cudaGetSymbolAddress(&qkv_ptr, g_qkv);
    cudaGetSymbolAddress(&att_ptr, g_att);

    const int gemm_smem = (2 * AS_WORDS + 2 * BS_WORDS) * 4;  // ~70KB
    static bool attr_set = false;
    if (!attr_set) {
        cudaFuncSetAttribute((const void*)gemm_tc_kernel<384, true>,
                             cudaFuncAttributeMaxDynamicSharedMemorySize, gemm_smem);
        cudaFuncSetAttribute((const void*)gemm_tc_kernel<128, false>,
                             cudaFuncAttributeMaxDynamicSharedMemorySize, gemm_smem);
        attr_set = true;
    }

    // bias+mask fusion table
    bm_kernel<<<(NWIN * N_TOK * N_TOK + 255) / 256, 256>>>(mask, bias_table, rel_index);

    // Stage A: qkv (tf32 bits, q pre-scaled)
    gemm_tc_kernel<384, true><<<dim3(M_ROWS / 128, 384 / 128), 256, gemm_smem>>>(
        x, qkv_w, qkv_b, (float*)qkv_ptr);

    // Stage B: single-barrier tensor-core windowed attention
    attn_tc_kernel<<<dim3(B_WIN, NH), 128>>>();

    // Stage C: out = att @ proj_w + proj_b
    gemm_tc_kernel<128, false><<<dim3(M_ROWS / 128, 128 / 128), 256, gemm_smem>>>(
        (const float*)att_ptr, proj_w, proj_b, out);
}